// round 4
// baseline (speedup 1.0000x reference)
#include <cuda_runtime.h>
#include <cuda_bf16.h>
#include <cstdint>

// Histogram_15126874816754:
//   out[b, (p>0), y, x] += |p|/STD  over N events, then clip at 1.0.
// Inputs: x:int32[N], y:int32[N], p:f32[N], b:int32[N], width, height, batch.
// Output: f32[B*2*H*W] = 14.75M floats (59 MB -> kept L2-resident via
// evict_last policy; zero/scatter/clip all operate at L2 speed).

#define INV_STD_C  (1.0f / 20.0f)
#define CLIP_MAX_C 1.0f

#define ZERO_BLOCKS 1024
#define CLIP_BLOCKS 1024

__device__ __forceinline__ uint64_t make_evict_last_policy() {
    uint64_t pol;
    asm("createpolicy.fractional.L2::evict_last.b64 %0, 1.0;" : "=l"(pol));
    return pol;
}

__device__ __forceinline__ void red_add_f32_evict_last(float* p, float v, uint64_t pol) {
    asm volatile(
        "red.relaxed.gpu.global.L2::cache_hint.add.f32 [%0], %1, %2;"
        :: "l"(p), "f"(v), "l"(pol) : "memory");
}

__device__ __forceinline__ void st_zero4_evict_last(float4* p, uint64_t pol) {
    const float z = 0.0f;
    asm volatile(
        "st.global.L2::cache_hint.v4.f32 [%0], {%1, %1, %1, %1}, %2;"
        :: "l"(p), "f"(z), "l"(pol) : "memory");
}

// ---------------------------------------------------------------------------
// Zero pass: grid-stride, 8 x float4 stores per iteration (MLP=8).
// Stores carry evict_last so the image is L2-resident before the scatter.
// ---------------------------------------------------------------------------
__global__ void __launch_bounds__(256)
hist_zero_kernel(float* __restrict__ out, int n)
{
    const uint64_t pol = make_evict_last_policy();
    float4* o4 = reinterpret_cast<float4*>(out);
    const int n4 = n >> 2;

    const int stride  = gridDim.x * blockDim.x;          // threads total
    const int chunk   = stride * 8;                      // float4s per sweep
    int base = blockIdx.x * blockDim.x + threadIdx.x;

    // full 8-wide sweeps
    int i = base;
    for (; i + 7 * stride < n4; i += chunk) {
#pragma unroll
        for (int j = 0; j < 8; ++j)
            st_zero4_evict_last(o4 + i + j * stride, pol);
    }
    // remaining float4s
    for (; i < n4; i += stride)
        st_zero4_evict_last(o4 + i, pol);
    // scalar tail
    if (base == 0)
        for (int k = n4 * 4; k < n; ++k) out[k] = 0.0f;
}

// ---------------------------------------------------------------------------
// Scatter: 8 events/thread, front-batched streaming loads (__ldcs, evict
// first), evict_last REDs. Near the per-SM LSU floor per the HW model.
// ---------------------------------------------------------------------------
__global__ void __launch_bounds__(256)
hist_scatter_kernel(const int4* __restrict__ xs,
                    const int4* __restrict__ ys,
                    const float4* __restrict__ ps,
                    const int4* __restrict__ bs,
                    const int* __restrict__ wp,
                    const int* __restrict__ hp,
                    float* __restrict__ out,
                    int n8)
{
    const int W = __ldg(wp);
    const int H = __ldg(hp);
    const uint64_t pol = make_evict_last_policy();

    const int i = blockIdx.x * blockDim.x + threadIdx.x;
    if (i >= n8) return;

    const int4   x0 = __ldcs(xs + 2 * i),  x1 = __ldcs(xs + 2 * i + 1);
    const int4   y0 = __ldcs(ys + 2 * i),  y1 = __ldcs(ys + 2 * i + 1);
    const float4 p0 = __ldcs(ps + 2 * i),  p1 = __ldcs(ps + 2 * i + 1);
    const int4   b0 = __ldcs(bs + 2 * i),  b1 = __ldcs(bs + 2 * i + 1);

#define SCATTER_ONE(xx, yy, pp, bb)                                        \
    {                                                                      \
        const int pos = (pp) > 0.0f;                                       \
        const int idx = (((bb) * 2 + pos) * H + (yy)) * W + (xx);          \
        red_add_f32_evict_last(out + idx, fabsf(pp) * INV_STD_C, pol);     \
    }

    SCATTER_ONE(x0.x, y0.x, p0.x, b0.x)
    SCATTER_ONE(x0.y, y0.y, p0.y, b0.y)
    SCATTER_ONE(x0.z, y0.z, p0.z, b0.z)
    SCATTER_ONE(x0.w, y0.w, p0.w, b0.w)
    SCATTER_ONE(x1.x, y1.x, p1.x, b1.x)
    SCATTER_ONE(x1.y, y1.y, p1.y, b1.y)
    SCATTER_ONE(x1.z, y1.z, p1.z, b1.z)
    SCATTER_ONE(x1.w, y1.w, p1.w, b1.w)
#undef SCATTER_ONE
}

__global__ void
hist_scatter_tail_kernel(const int* __restrict__ xs,
                         const int* __restrict__ ys,
                         const float* __restrict__ ps,
                         const int* __restrict__ bs,
                         const int* __restrict__ wp,
                         const int* __restrict__ hp,
                         float* __restrict__ out,
                         int start, int n)
{
    const int k = start + blockIdx.x * blockDim.x + threadIdx.x;
    if (k >= n) return;
    const int W = __ldg(wp);
    const int H = __ldg(hp);
    const float pk = ps[k];
    const int pos = pk > 0.0f;
    const int idx = ((bs[k] * 2 + pos) * H + ys[k]) * W + xs[k];
    atomicAdd(out + idx, fabsf(pk) * INV_STD_C);
}

// ---------------------------------------------------------------------------
// Clip pass: grid-stride, 8 x float4 loads per iteration; store only when a
// component exceeds 1.0 (rare), so the write stream nearly vanishes.
// ---------------------------------------------------------------------------
__global__ void __launch_bounds__(256)
hist_clip_kernel(float* __restrict__ out, int n)
{
    float4* o4 = reinterpret_cast<float4*>(out);
    const int n4 = n >> 2;

    const int stride = gridDim.x * blockDim.x;
    const int chunk  = stride * 8;
    const int base   = blockIdx.x * blockDim.x + threadIdx.x;

    int i = base;
    for (; i + 7 * stride < n4; i += chunk) {
        float4 v[8];
#pragma unroll
        for (int j = 0; j < 8; ++j)
            v[j] = __ldg(o4 + i + j * stride);
#pragma unroll
        for (int j = 0; j < 8; ++j) {
            if (v[j].x > CLIP_MAX_C || v[j].y > CLIP_MAX_C ||
                v[j].z > CLIP_MAX_C || v[j].w > CLIP_MAX_C) {
                float4 w = v[j];
                w.x = fminf(w.x, CLIP_MAX_C);
                w.y = fminf(w.y, CLIP_MAX_C);
                w.z = fminf(w.z, CLIP_MAX_C);
                w.w = fminf(w.w, CLIP_MAX_C);
                o4[i + j * stride] = w;
            }
        }
    }
    for (; i < n4; i += stride) {
        float4 v = __ldg(o4 + i);
        if (v.x > CLIP_MAX_C || v.y > CLIP_MAX_C ||
            v.z > CLIP_MAX_C || v.w > CLIP_MAX_C) {
            v.x = fminf(v.x, CLIP_MAX_C);
            v.y = fminf(v.y, CLIP_MAX_C);
            v.z = fminf(v.z, CLIP_MAX_C);
            v.w = fminf(v.w, CLIP_MAX_C);
            o4[i] = v;
        }
    }
    if (base == 0) {
        for (int k = n4 * 4; k < n; ++k) {
            const float v = out[k];
            if (v > CLIP_MAX_C) out[k] = CLIP_MAX_C;
        }
    }
}

// ---------------------------------------------------------------------------
extern "C" void kernel_launch(void* const* d_in, const int* in_sizes, int n_in,
                              void* d_out, int out_size)
{
    const int*   xs = (const int*)  d_in[0];
    const int*   ys = (const int*)  d_in[1];
    const float* ps = (const float*)d_in[2];
    const int*   bs = (const int*)  d_in[3];
    const int*   wp = (const int*)  d_in[4];
    const int*   hp = (const int*)  d_in[5];

    float* out = (float*)d_out;
    const int n = in_sizes[0];

    // 1) zero (grid-stride, evict_last stores -> image L2-resident)
    hist_zero_kernel<<<ZERO_BLOCKS, 256>>>(out, out_size);

    // 2) scatter-add (8 events/thread)
    {
        const int n8 = n >> 3;
        if (n8 > 0) {
            const int blocks = (n8 + 255) / 256;
            hist_scatter_kernel<<<blocks, 256>>>(
                (const int4*)xs, (const int4*)ys, (const float4*)ps,
                (const int4*)bs, wp, hp, out, n8);
        }
        if (n & 7) {
            hist_scatter_tail_kernel<<<1, 32>>>(xs, ys, ps, bs, wp, hp,
                                                out, n & ~7, n);
        }
    }

    // 3) clip (grid-stride, conditional store)
    hist_clip_kernel<<<CLIP_BLOCKS, 256>>>(out, out_size);
}